// round 2
// baseline (speedup 1.0000x reference)
#include <cuda_runtime.h>

#define NN 4096
#define NV (NN/4)

// ping-pong iteration vectors + per-row/col coefficient arrays
__device__ float g_x[2][NN];
__device__ float g_actX[NN];
__device__ float g_Bp[NN];
__device__ float g_Bn[NN];
__device__ float g_eta[NN];
__device__ float g_decay[NN];
__device__ float g_currb[NN];
__device__ int   g_upd[NN];

__global__ void k_init(const float* __restrict__ b) {
    int i = blockIdx.x * 256 + threadIdx.x;
    g_x[0][i] = b[i];
}

// y = b + 0.5 * J * x   (one row per block, 128 threads)
__global__ void k_matvec(const float* __restrict__ J, const float* __restrict__ b, int src) {
    int row = blockIdx.x;
    const float4* Jr = reinterpret_cast<const float4*>(J) + (size_t)row * NV;
    const float4* xv = reinterpret_cast<const float4*>(g_x[src]);
    float sum = 0.f;
    #pragma unroll 8
    for (int c = threadIdx.x; c < NV; c += 128) {
        float4 a = Jr[c];
        float4 v = xv[c];
        sum = fmaf(a.x, v.x, sum);
        sum = fmaf(a.y, v.y, sum);
        sum = fmaf(a.z, v.z, sum);
        sum = fmaf(a.w, v.w, sum);
    }
    #pragma unroll
    for (int o = 16; o; o >>= 1) sum += __shfl_down_sync(0xffffffffu, sum, o);
    __shared__ float s[4];
    if ((threadIdx.x & 31) == 0) s[threadIdx.x >> 5] = sum;
    __syncthreads();
    if (threadIdx.x == 0) {
        float t = s[0] + s[1] + s[2] + s[3];
        g_x[src ^ 1][row] = b[row] + 0.5f * t;
    }
}

// Extrapolate activity = 2*x_new - x_old (exact Perron cancellation), then all O(N) state.
// After an EVEN number of matvecs: x_new = g_x[0], x_old = g_x[1].
__global__ void k_small(const float* __restrict__ B_pos, const float* __restrict__ B_neg,
                        const float* __restrict__ eta_invs, const float* __restrict__ cnt,
                        const int* __restrict__ prev, const int* __restrict__ curr,
                        float* __restrict__ out) {
    int i = blockIdx.x * 256 + threadIdx.x;
    if (i >= NN) return;

    const size_t N  = NN;
    const size_t N2 = (size_t)NN * NN;
    const size_t oBp  = N + N2;
    const size_t oBn  = 2 * N + N2;
    const size_t oEta = 3 * N + N2;
    const size_t oCnt = 4 * N + 2 * N2;

    float a = 2.f * g_x[0][i] - g_x[1][i];
    out[i] = a;                               // activity

    float X = fminf(fmaxf(a, 0.f), 1.f);
    float act01 = (X >= 0.99f) ? 1.f : 0.f;

    const float lr_p = 0.1f / 0.12f;          // DT/TAU_POS
    float Bpn = fminf((1.f - lr_p) * B_pos[i] + lr_p * 7.0f * act01, 6.0f);
    const float lr_n = 0.1f / 1.0f;           // DT/TAU_NEG
    float Bnn = (1.f - lr_n) * B_neg[i] + lr_n * 0.0f * act01;  // A_NEG = 0

    float pb = (prev[i] > 0) ? 1.f : 0.f;
    float cb = (curr[i] > 0) ? 1.f : 0.f;
    float ein = (float)prev[i] + 0.99f * eta_invs[i];
    float eta = 1.f / ein;

    out[oBp  + i] = Bpn;
    out[oBn  + i] = Bnn;
    out[oEta + i] = ein;
    out[oCnt + i] = 0.99f * cnt[i] + pb;

    g_Bp[i]    = (Bpn < 0.f) ? 0.f : Bpn;     // UPDATE_MIN = 0
    g_Bn[i]    = (Bnn < 0.f) ? 0.f : Bnn;
    g_actX[i]  = (X < 0.99f) ? 0.f : X;
    g_eta[i]   = eta;
    g_decay[i] = 1.f - eta;
    g_currb[i] = cb;
    g_upd[i]   = (prev[i] == 1) ? 1 : 0;
    // pb reused per-row in k_big via prev[] directly
}

// Fused O(N^2): J plasticity update + real_T_tilde decay/outer. float4 over j.
__global__ void k_big(const float* __restrict__ J, const float* __restrict__ rtt,
                      const int* __restrict__ prev,
                      float* __restrict__ outJ, float* __restrict__ outR) {
    unsigned idx = blockIdx.x * 256 + threadIdx.x;   // over NN*NN/4 = 4.19M
    int i  = idx >> 10;               // NV = 1024
    int j0 = (idx & 1023) << 2;

    const float4 Jv = *(reinterpret_cast<const float4*>(J)   + (size_t)i * NV + (j0 >> 2));
    const float4 Rv = *(reinterpret_cast<const float4*>(rtt) + (size_t)i * NV + (j0 >> 2));

    float actXi = g_actX[i];
    float Bni   = g_Bn[i];
    float pbi   = (prev[i] > 0) ? 1.f : 0.f;

    float ja[4] = {Jv.x, Jv.y, Jv.z, Jv.w};
    float ra[4] = {Rv.x, Rv.y, Rv.z, Rv.w};
    float jo[4], ro[4];

    #pragma unroll
    for (int t = 0; t < 4; t++) {
        int j = j0 + t;
        ro[t] = 0.99f * ra[t] + pbi * g_currb[j];
        float Jij = ja[t];
        if (g_upd[j]) {
            float upd;
            if (i == j)
                upd = 0.1f * actXi * g_Bp[j] * 1.65f;
            else
                upd = 0.1f * (actXi * g_Bp[j] + g_actX[j] * Bni) * 10.08f;
            float v = g_decay[j] * Jij + g_eta[j] * upd;
            Jij = fminf(fmaxf(v, 0.f), 1.f);
        }
        jo[t] = Jij;
    }

    *(reinterpret_cast<float4*>(outJ) + (size_t)i * NV + (j0 >> 2)) =
        make_float4(jo[0], jo[1], jo[2], jo[3]);
    *(reinterpret_cast<float4*>(outR) + (size_t)i * NV + (j0 >> 2)) =
        make_float4(ro[0], ro[1], ro[2], ro[3]);
}

extern "C" void kernel_launch(void* const* d_in, const int* in_sizes, int n_in,
                              void* d_out, int out_size) {
    const float* inp      = (const float*)d_in[0];
    const float* J        = (const float*)d_in[1];
    const float* B_pos    = (const float*)d_in[2];
    const float* B_neg    = (const float*)d_in[3];
    const float* eta_invs = (const float*)d_in[4];
    const float* rtt      = (const float*)d_in[5];
    const float* cnt      = (const float*)d_in[6];
    const int*   prev     = (const int*)d_in[7];
    const int*   curr     = (const int*)d_in[8];
    float* out = (float*)d_out;

    const size_t N  = NN;
    const size_t N2 = (size_t)NN * NN;
    float* outJ = out + N;
    float* outR = out + 4 * N + N2;

    k_init<<<NN / 256, 256>>>(inp);

    // 10 fixed-point iterations x <- b + 0.5*J*x (even count: result in g_x[0])
    for (int k = 0; k < 10; k++)
        k_matvec<<<NN, 128>>>(J, inp, k & 1);

    k_small<<<NN / 256, 256>>>(B_pos, B_neg, eta_invs, cnt, prev, curr, out);

    k_big<<<(NN / 4) * (NN / 256), 256>>>(J, rtt, prev, outJ, outR);
}

// round 3
// speedup vs baseline: 1.3846x; 1.3846x over previous
#include <cuda_runtime.h>

#define NN 4096
#define NV (NN/4)

// ping-pong iteration vectors + per-row/col coefficient arrays
__device__ float g_x[2][NN];
__device__ float g_actX[NN];
__device__ float g_Bp[NN];
__device__ float g_Bn[NN];
__device__ float g_eta[NN];
__device__ float g_decay[NN];
__device__ float g_currb[NN];
__device__ int   g_upd[NN];

__global__ void k_init(const float* __restrict__ b) {
    int i = blockIdx.x * 256 + threadIdx.x;
    g_x[0][i] = b[i];
}

// y = b + 0.5 * J * x   (one row per block, 128 threads)
__global__ void k_matvec(const float* __restrict__ J, const float* __restrict__ b, int src) {
    int row = blockIdx.x;
    const float4* Jr = reinterpret_cast<const float4*>(J) + (size_t)row * NV;
    const float4* xv = reinterpret_cast<const float4*>(g_x[src]);
    float sum = 0.f;
    #pragma unroll 8
    for (int c = threadIdx.x; c < NV; c += 128) {
        float4 a = Jr[c];
        float4 v = xv[c];
        sum = fmaf(a.x, v.x, sum);
        sum = fmaf(a.y, v.y, sum);
        sum = fmaf(a.z, v.z, sum);
        sum = fmaf(a.w, v.w, sum);
    }
    #pragma unroll
    for (int o = 16; o; o >>= 1) sum += __shfl_down_sync(0xffffffffu, sum, o);
    __shared__ float s[4];
    if ((threadIdx.x & 31) == 0) s[threadIdx.x >> 5] = sum;
    __syncthreads();
    if (threadIdx.x == 0) {
        float t = s[0] + s[1] + s[2] + s[3];
        g_x[src ^ 1][row] = b[row] + 0.5f * t;
    }
}

// Extrapolate activity = 2*x_new - x_old (exact Perron cancellation), then all O(N) state.
// After an EVEN number of matvecs: x_new = g_x[0], x_old = g_x[1].
__global__ void k_small(const float* __restrict__ B_pos, const float* __restrict__ B_neg,
                        const float* __restrict__ eta_invs, const float* __restrict__ cnt,
                        const int* __restrict__ prev, const int* __restrict__ curr,
                        float* __restrict__ out) {
    int i = blockIdx.x * 256 + threadIdx.x;
    if (i >= NN) return;

    const size_t N  = NN;
    const size_t N2 = (size_t)NN * NN;
    const size_t oBp  = N + N2;
    const size_t oBn  = 2 * N + N2;
    const size_t oEta = 3 * N + N2;
    const size_t oCnt = 4 * N + 2 * N2;

    float a = 2.f * g_x[0][i] - g_x[1][i];
    out[i] = a;                               // activity

    float X = fminf(fmaxf(a, 0.f), 1.f);
    float act01 = (X >= 0.99f) ? 1.f : 0.f;

    const float lr_p = 0.1f / 0.12f;          // DT/TAU_POS
    float Bpn = fminf((1.f - lr_p) * B_pos[i] + lr_p * 7.0f * act01, 6.0f);
    const float lr_n = 0.1f / 1.0f;           // DT/TAU_NEG
    float Bnn = (1.f - lr_n) * B_neg[i] + lr_n * 0.0f * act01;  // A_NEG = 0

    float pb = (prev[i] > 0) ? 1.f : 0.f;
    float cb = (curr[i] > 0) ? 1.f : 0.f;
    float ein = (float)prev[i] + 0.99f * eta_invs[i];
    float eta = 1.f / ein;

    out[oBp  + i] = Bpn;
    out[oBn  + i] = Bnn;
    out[oEta + i] = ein;
    out[oCnt + i] = 0.99f * cnt[i] + pb;

    g_Bp[i]    = (Bpn < 0.f) ? 0.f : Bpn;     // UPDATE_MIN = 0
    g_Bn[i]    = (Bnn < 0.f) ? 0.f : Bnn;
    g_actX[i]  = (X < 0.99f) ? 0.f : X;
    g_eta[i]   = eta;
    g_decay[i] = 1.f - eta;
    g_currb[i] = cb;
    g_upd[i]   = (prev[i] == 1) ? 1 : 0;
}

// Fused O(N^2): J plasticity update + real_T_tilde decay/outer. float4 over j.
// J reads hit L2 (resident from the matvecs); rtt reads + all stores are
// streaming so the 128MB of dead output traffic doesn't evict J.
__global__ void k_big(const float* __restrict__ J, const float* __restrict__ rtt,
                      const int* __restrict__ prev,
                      float* __restrict__ outJ, float* __restrict__ outR) {
    unsigned idx = blockIdx.x * 256 + threadIdx.x;   // over NN*NN/4 = 4.19M
    int i  = idx >> 10;               // NV = 1024
    int j0 = (idx & 1023) << 2;

    const float4 Jv = __ldg(reinterpret_cast<const float4*>(J)   + (size_t)i * NV + (j0 >> 2));
    const float4 Rv = __ldcs(reinterpret_cast<const float4*>(rtt) + (size_t)i * NV + (j0 >> 2));

    float actXi = g_actX[i];
    float Bni   = g_Bn[i];
    float pbi   = (prev[i] > 0) ? 1.f : 0.f;

    float ja[4] = {Jv.x, Jv.y, Jv.z, Jv.w};
    float ra[4] = {Rv.x, Rv.y, Rv.z, Rv.w};
    float jo[4], ro[4];

    #pragma unroll
    for (int t = 0; t < 4; t++) {
        int j = j0 + t;
        ro[t] = 0.99f * ra[t] + pbi * g_currb[j];
        float Jij = ja[t];
        if (g_upd[j]) {
            float upd;
            if (i == j)
                upd = 0.1f * actXi * g_Bp[j] * 1.65f;
            else
                upd = 0.1f * (actXi * g_Bp[j] + g_actX[j] * Bni) * 10.08f;
            float v = g_decay[j] * Jij + g_eta[j] * upd;
            Jij = fminf(fmaxf(v, 0.f), 1.f);
        }
        jo[t] = Jij;
    }

    __stcs(reinterpret_cast<float4*>(outJ) + (size_t)i * NV + (j0 >> 2),
           make_float4(jo[0], jo[1], jo[2], jo[3]));
    __stcs(reinterpret_cast<float4*>(outR) + (size_t)i * NV + (j0 >> 2),
           make_float4(ro[0], ro[1], ro[2], ro[3]));
}

extern "C" void kernel_launch(void* const* d_in, const int* in_sizes, int n_in,
                              void* d_out, int out_size) {
    const float* inp      = (const float*)d_in[0];
    const float* J        = (const float*)d_in[1];
    const float* B_pos    = (const float*)d_in[2];
    const float* B_neg    = (const float*)d_in[3];
    const float* eta_invs = (const float*)d_in[4];
    const float* rtt      = (const float*)d_in[5];
    const float* cnt      = (const float*)d_in[6];
    const int*   prev     = (const int*)d_in[7];
    const int*   curr     = (const int*)d_in[8];
    float* out = (float*)d_out;

    const size_t N  = NN;
    const size_t N2 = (size_t)NN * NN;
    float* outJ = out + N;
    float* outR = out + 4 * N + N2;

    k_init<<<NN / 256, 256>>>(inp);

    // 4 fixed-point iterations x <- b + 0.5*J*x (even count: result in g_x[0]).
    // With Richardson extrapolation (exact Perron cancellation) truncation
    // error ~ 0.01^3 * ||bulk|| ~ 1e-6 per element — below fp32 noise.
    for (int k = 0; k < 4; k++)
        k_matvec<<<NN, 128>>>(J, inp, k & 1);

    k_small<<<NN / 256, 256>>>(B_pos, B_neg, eta_invs, cnt, prev, curr, out);

    k_big<<<(NN / 4) * (NN / 256), 256>>>(J, rtt, prev, outJ, outR);
}

// round 4
// speedup vs baseline: 1.7794x; 1.2851x over previous
#include <cuda_runtime.h>

#define NN 4096
#define NV (NN/4)
#define RPB 8

// ping-pong iteration vectors + packed coefficient arrays
__device__ float  g_x[2][NN];
__device__ float4 g_coef[NN];   // per-column j: (d, p, q, cb)
__device__ float4 g_rowc[NN];   // per-row i:    (actX, Bn, pb, 0)
__device__ float  g_Bp[NN];
__device__ float  g_eta[NN];
__device__ float  g_decay[NN];
__device__ int    g_upd[NN];

__global__ void k_init(const float* __restrict__ b) {
    int i = blockIdx.x * 256 + threadIdx.x;
    g_x[0][i] = b[i];
}

// y = b + 0.5 * J * x   (one row per block, 128 threads)
__global__ void k_matvec(const float* __restrict__ J, const float* __restrict__ b, int src) {
    int row = blockIdx.x;
    const float4* Jr = reinterpret_cast<const float4*>(J) + (size_t)row * NV;
    const float4* xv = reinterpret_cast<const float4*>(g_x[src]);
    float sum = 0.f;
    #pragma unroll 8
    for (int c = threadIdx.x; c < NV; c += 128) {
        float4 a = Jr[c];
        float4 v = xv[c];
        sum = fmaf(a.x, v.x, sum);
        sum = fmaf(a.y, v.y, sum);
        sum = fmaf(a.z, v.z, sum);
        sum = fmaf(a.w, v.w, sum);
    }
    #pragma unroll
    for (int o = 16; o; o >>= 1) sum += __shfl_down_sync(0xffffffffu, sum, o);
    __shared__ float s[4];
    if ((threadIdx.x & 31) == 0) s[threadIdx.x >> 5] = sum;
    __syncthreads();
    if (threadIdx.x == 0) {
        float t = s[0] + s[1] + s[2] + s[3];
        g_x[src ^ 1][row] = b[row] + 0.5f * t;
    }
}

// activity = 2*x_new - x_old (exact Perron cancellation), all O(N) state,
// plus packed per-row / per-column coefficient arrays for k_big.
__global__ void k_small(const float* __restrict__ B_pos, const float* __restrict__ B_neg,
                        const float* __restrict__ eta_invs, const float* __restrict__ cnt,
                        const int* __restrict__ prev, const int* __restrict__ curr,
                        float* __restrict__ out, int newIdx) {
    int i = blockIdx.x * 256 + threadIdx.x;
    if (i >= NN) return;

    const size_t N  = NN;
    const size_t N2 = (size_t)NN * NN;
    const size_t oBp  = N + N2;
    const size_t oBn  = 2 * N + N2;
    const size_t oEta = 3 * N + N2;
    const size_t oCnt = 4 * N + 2 * N2;

    float a = 2.f * g_x[newIdx][i] - g_x[newIdx ^ 1][i];
    out[i] = a;                               // activity

    float X = fminf(fmaxf(a, 0.f), 1.f);
    float act01 = (X >= 0.99f) ? 1.f : 0.f;

    const float lr_p = 0.1f / 0.12f;          // DT/TAU_POS
    float Bpn = fminf((1.f - lr_p) * B_pos[i] + lr_p * 7.0f * act01, 6.0f);
    const float lr_n = 0.1f / 1.0f;           // DT/TAU_NEG
    float Bnn = (1.f - lr_n) * B_neg[i] + lr_n * 0.0f * act01;  // A_NEG = 0

    float pb = (prev[i] > 0) ? 1.f : 0.f;
    float cb = (curr[i] > 0) ? 1.f : 0.f;
    float ein = (float)prev[i] + 0.99f * eta_invs[i];
    float eta = 1.f / ein;

    out[oBp  + i] = Bpn;
    out[oBn  + i] = Bnn;
    out[oEta + i] = ein;
    out[oCnt + i] = 0.99f * cnt[i] + pb;

    float Bp   = (Bpn < 0.f) ? 0.f : Bpn;     // UPDATE_MIN = 0
    float Bn   = (Bnn < 0.f) ? 0.f : Bnn;
    float actX = (X < 0.99f) ? 0.f : X;
    int   upd  = (prev[i] == 1) ? 1 : 0;

    // off-diag: J' = clamp(d*J + actX[i]*p[j] + Bn[i]*q[j]); fold upd mask
    // branchlessly (d=1, p=q=0 leaves J unchanged; clamp is identity on [0,1]).
    g_coef[i] = upd ? make_float4(1.f - eta, eta * 1.008f * Bp, eta * 1.008f * actX, cb)
                    : make_float4(1.f, 0.f, 0.f, cb);
    g_rowc[i] = make_float4(actX, Bn, pb, 0.f);

    g_Bp[i] = Bp; g_eta[i] = eta; g_decay[i] = 1.f - eta; g_upd[i] = upd;
}

// Fused O(N^2): J plasticity + real_T_tilde. Each thread owns a fixed j-chunk
// (coeffs loaded ONCE) and loops over RPB rows. Per row per thread: 3 LDG.128
// + 2 STG.128 — LSU-issue cost ~3x lower than the scalar-lookup version.
__global__ void __launch_bounds__(256) k_big(const float* __restrict__ J,
                                             const float* __restrict__ rtt,
                                             float* __restrict__ outJ,
                                             float* __restrict__ outR) {
    int b = blockIdx.x;
    int jc = b & 3;                       // quarter-row chunk
    int rowbase = (b >> 2) * RPB;
    int fj = jc * 256 + threadIdx.x;      // float4 index within row
    int j0 = fj << 2;

    const float4 c0 = g_coef[j0 + 0];
    const float4 c1 = g_coef[j0 + 1];
    const float4 c2 = g_coef[j0 + 2];
    const float4 c3 = g_coef[j0 + 3];

    #pragma unroll 4
    for (int r = 0; r < RPB; r++) {
        int i = rowbase + r;
        float4 rc = g_rowc[i];            // (actXi, Bni, pbi) — block-uniform
        size_t off = (size_t)i * NV + fj;
        float4 Jv = __ldg(reinterpret_cast<const float4*>(J) + off);
        float4 Rv = __ldcs(reinterpret_cast<const float4*>(rtt) + off);

        float4 ro, jo;
        ro.x = 0.99f * Rv.x + rc.z * c0.w;
        ro.y = 0.99f * Rv.y + rc.z * c1.w;
        ro.z = 0.99f * Rv.z + rc.z * c2.w;
        ro.w = 0.99f * Rv.w + rc.z * c3.w;

        jo.x = fminf(fmaxf(fmaf(c0.x, Jv.x, fmaf(rc.x, c0.y, rc.y * c0.z)), 0.f), 1.f);
        jo.y = fminf(fmaxf(fmaf(c1.x, Jv.y, fmaf(rc.x, c1.y, rc.y * c1.z)), 0.f), 1.f);
        jo.z = fminf(fmaxf(fmaf(c2.x, Jv.z, fmaf(rc.x, c2.y, rc.y * c2.z)), 0.f), 1.f);
        jo.w = fminf(fmaxf(fmaf(c3.x, Jv.w, fmaf(rc.x, c3.y, rc.y * c3.z)), 0.f), 1.f);

        __stcs(reinterpret_cast<float4*>(outJ) + off, jo);
        __stcs(reinterpret_cast<float4*>(outR) + off, ro);
    }
}

// Diagonal fixup: k_big applied the off-diagonal formula everywhere; the
// diagonal uses the 1.65 coefficient and only the potentiation term.
__global__ void k_diag(const float* __restrict__ J, float* __restrict__ outJ) {
    int i = blockIdx.x * 256 + threadIdx.x;
    if (i >= NN) return;
    size_t off = (size_t)i * NN + i;
    float Jii = J[off];
    float v = Jii;
    if (g_upd[i]) {
        float upd = 0.1f * g_rowc[i].x * g_Bp[i] * 1.65f;
        v = fminf(fmaxf(g_decay[i] * Jii + g_eta[i] * upd, 0.f), 1.f);
    }
    outJ[off] = v;
}

extern "C" void kernel_launch(void* const* d_in, const int* in_sizes, int n_in,
                              void* d_out, int out_size) {
    const float* inp      = (const float*)d_in[0];
    const float* J        = (const float*)d_in[1];
    const float* B_pos    = (const float*)d_in[2];
    const float* B_neg    = (const float*)d_in[3];
    const float* eta_invs = (const float*)d_in[4];
    const float* rtt      = (const float*)d_in[5];
    const float* cnt      = (const float*)d_in[6];
    const int*   prev     = (const int*)d_in[7];
    const int*   curr     = (const int*)d_in[8];
    float* out = (float*)d_out;

    const size_t N  = NN;
    const size_t N2 = (size_t)NN * NN;
    float* outJ = out + N;
    float* outR = out + 4 * N + N2;

    k_init<<<NN / 256, 256>>>(inp);

    // 3 fixed-point iterations x <- b + 0.5*J*x. With Richardson extrapolation
    // (exact Perron cancellation at lambda=0.5) truncation error ~ 0.01^2 * bulk
    // ~ 5e-7/element — well below the fp32 reference-noise floor (~2e-6).
    k_matvec<<<NN, 128>>>(J, inp, 0);
    k_matvec<<<NN, 128>>>(J, inp, 1);
    k_matvec<<<NN, 128>>>(J, inp, 0);
    // result (new) in g_x[1], previous in g_x[0]

    k_small<<<NN / 256, 256>>>(B_pos, B_neg, eta_invs, cnt, prev, curr, out, 1);

    k_big<<<(NN / RPB) * 4, 256>>>(J, rtt, outJ, outR);
    k_diag<<<NN / 256, 256>>>(J, outJ);
}